// round 16
// baseline (speedup 1.0000x reference)
#include <cuda_runtime.h>
#include <math.h>
#include <cstdint>

#define N 4096
#define D 128
#define NBINS 2048
#define NT 256
#define NWARP (NT / 32)
#define LTILES 32                 // N/128 (row tiles)
#define CTILES 64                 // N/64  (col tiles)
#define NGRAM 1056                // sum_{bi}(64-2bi)
#define PITCH 36                  // smem row pitch (floats)

__device__ float  g_logits[(size_t)N * N];  // 64 MB scratch: logits = -dist/2
__device__ float  g_fhi[(size_t)N * D];     // tf32-truncated hi part
__device__ float  g_flo[(size_t)N * D];     // tf32-truncated residual
__device__ float  g_x2[N];
__device__ double g_rowsum[N];
__device__ int    g_done;

// ---------------------------------------------------------------------------
// fast math on FMA/ALU pipes (MUFU avoidance)
// ---------------------------------------------------------------------------
__device__ __forceinline__ float fast_sqrt(float x) {
    float xh = 0.5f * x;
    float y = __int_as_float(0x5f375a86 - (__float_as_int(x) >> 1));
    y = y * fmaf(-xh * y, y, 1.5f);
    y = y * fmaf(-xh * y, y, 1.5f);
    y = y * fmaf(-xh * y, y, 1.5f);
    return x * y;
}
__device__ __forceinline__ float fast_exp(float x) {
    float t = x * 1.4426950408889634f;
    float n = rintf(t);
    float f = t - n;
    float p = fmaf(f, 1.5403530e-4f, 0.0013333558f);
    p = fmaf(f, p, 0.0096181291f);
    p = fmaf(f, p, 0.0555041087f);
    p = fmaf(f, p, 0.2402265069f);
    p = fmaf(f, p, 0.6931471806f);
    p = fmaf(f, p, 1.0f);
    return __int_as_float(((int)n + 127) << 23) * p;
}
__device__ __forceinline__ float tf32_rna(float x) {
    uint32_t r;
    asm("cvt.rna.tf32.f32 %0, %1;" : "=r"(r) : "f"(x));
    return __uint_as_float(r);
}

// ---------------------------------------------------------------------------
// Kernel 0: x2 + tf32 hi/lo split + counter reset
// ---------------------------------------------------------------------------
__global__ void prep_kernel(const float* __restrict__ F) {
    int i = blockIdx.x, t = threadIdx.x;
    if (i == 0 && t == 0) g_done = 0;
    float x = F[(size_t)i * D + t];
    float hi = tf32_rna(x);
    float lo = tf32_rna(x - hi);
    g_fhi[(size_t)i * D + t] = hi;
    g_flo[(size_t)i * D + t] = lo;
    float v = x * x;
    __shared__ float s[4];
    #pragma unroll
    for (int o = 16; o; o >>= 1) v += __shfl_down_sync(0xffffffffu, v, o);
    if ((t & 31) == 0) s[t >> 5] = v;
    __syncthreads();
    if (t == 0) g_x2[i] = s[0] + s[1] + s[2] + s[3];
}

// profiler-alignment spacer (ncu profiles absolute launch #4)
__global__ void nop_kernel() {}

// ---------------------------------------------------------------------------
// Kernel 1: tf32 tensor-core Gram, 128x64 tiles, warp tiling (mt,nt)=(2,4)
// to minimize fragment LDS (32 vs 40 per warp per k-slice).
// Tiles (bi, cj) with cj >= 2*bi: diagonal-straddling pair computed fully,
// strict-upper tiles mirrored.
// ---------------------------------------------------------------------------
#define MMA_TF32(c, a, b) \
    asm volatile("mma.sync.aligned.m16n8k8.row.col.f32.tf32.tf32.f32 " \
        "{%0,%1,%2,%3}, {%4,%5,%6,%7}, {%8,%9}, {%0,%1,%2,%3};" \
        : "+f"((c)[0]), "+f"((c)[1]), "+f"((c)[2]), "+f"((c)[3]) \
        : "r"((a)[0]), "r"((a)[1]), "r"((a)[2]), "r"((a)[3]), \
          "r"((b)[0]), "r"((b)[1]))

__global__ void __launch_bounds__(256, 2) gram_kernel() {
    // decode linear index -> (bi, cj), cj in [2*bi, 64)
    int idx = blockIdx.x;
    int bi = 0;
    #pragma unroll 1
    for (;; bi++) {
        int cnt = CTILES - 2 * bi;
        if (idx < cnt) break;
        idx -= cnt;
    }
    int cj = 2 * bi + idx;
    bool mirror = (cj >= 2 * bi + 2);

    extern __shared__ __align__(16) float smf[];
    float* Ah = smf;                        // 128 x PITCH
    float* Al = Ah + 128 * PITCH;           // 128 x PITCH
    float* Bh = Al + 128 * PITCH;           // 64 x PITCH
    float* Bl = Bh + 64 * PITCH;            // 64 x PITCH

    const int t = threadIdx.x;
    const int wid = t >> 5, lane = t & 31;
    const int g = lane >> 2, tid4 = lane & 3;
    const int rm = (wid & 3) * 32;          // warp row base (0,32,64,96)
    const int rn = (wid >> 2) * 32;         // warp col base (0 or 32)

    float acc[2][4][4];
    #pragma unroll
    for (int mt = 0; mt < 2; mt++)
        #pragma unroll
        for (int nt = 0; nt < 4; nt++)
            #pragma unroll
            for (int e = 0; e < 4; e++) acc[mt][nt][e] = 0.f;

    #pragma unroll 1
    for (int kc = 0; kc < 4; kc++) {
        int k0 = kc * 32;
        __syncthreads();
        // A tiles: 128 rows x 8 float4-chunks, hi+lo
        #pragma unroll
        for (int p = 0; p < 4; p++) {
            int id = t + p * 256;
            int row = id >> 3, cg = id & 7;
            size_t arow = (size_t)(bi * 128 + row) * D + k0;
            *(float4*)&Ah[row * PITCH + cg * 4] = *(const float4*)(g_fhi + arow + cg * 4);
            *(float4*)&Al[row * PITCH + cg * 4] = *(const float4*)(g_flo + arow + cg * 4);
        }
        // B tiles: 64 rows x 8 chunks, hi+lo
        #pragma unroll
        for (int p = 0; p < 2; p++) {
            int id = t + p * 256;
            int row = id >> 3, cg = id & 7;
            size_t brow = (size_t)(cj * 64 + row) * D + k0;
            *(float4*)&Bh[row * PITCH + cg * 4] = *(const float4*)(g_fhi + brow + cg * 4);
            *(float4*)&Bl[row * PITCH + cg * 4] = *(const float4*)(g_flo + brow + cg * 4);
        }
        __syncthreads();

        #pragma unroll
        for (int ks = 0; ks < 4; ks++) {
            int kk = ks * 8;
            uint32_t afH[2][4], afL[2][4];
            #pragma unroll
            for (int mt = 0; mt < 2; mt++) {
                int r0 = rm + mt * 16 + g;
                afH[mt][0] = __float_as_uint(Ah[r0 * PITCH + kk + tid4]);
                afH[mt][1] = __float_as_uint(Ah[(r0 + 8) * PITCH + kk + tid4]);
                afH[mt][2] = __float_as_uint(Ah[r0 * PITCH + kk + tid4 + 4]);
                afH[mt][3] = __float_as_uint(Ah[(r0 + 8) * PITCH + kk + tid4 + 4]);
                afL[mt][0] = __float_as_uint(Al[r0 * PITCH + kk + tid4]);
                afL[mt][1] = __float_as_uint(Al[(r0 + 8) * PITCH + kk + tid4]);
                afL[mt][2] = __float_as_uint(Al[r0 * PITCH + kk + tid4 + 4]);
                afL[mt][3] = __float_as_uint(Al[(r0 + 8) * PITCH + kk + tid4 + 4]);
            }
            uint32_t bfH[4][2], bfL[4][2];
            #pragma unroll
            for (int nt = 0; nt < 4; nt++) {
                int nc = rn + nt * 8 + g;
                bfH[nt][0] = __float_as_uint(Bh[nc * PITCH + kk + tid4]);
                bfH[nt][1] = __float_as_uint(Bh[nc * PITCH + kk + tid4 + 4]);
                bfL[nt][0] = __float_as_uint(Bl[nc * PITCH + kk + tid4]);
                bfL[nt][1] = __float_as_uint(Bl[nc * PITCH + kk + tid4 + 4]);
            }
            #pragma unroll
            for (int mt = 0; mt < 2; mt++)
                #pragma unroll
                for (int nt = 0; nt < 4; nt++) {
                    MMA_TF32(acc[mt][nt], afH[mt], bfH[nt]);
                    MMA_TF32(acc[mt][nt], afH[mt], bfL[nt]);
                    MMA_TF32(acc[mt][nt], afL[mt], bfH[nt]);
                }
        }
    }

    // epilogue: logits = -0.5*sqrt(x2i + x2j - 2*dot); optional mirror
    #pragma unroll
    for (int mt = 0; mt < 2; mt++) {
        int gr0 = bi * 128 + rm + mt * 16 + g;
        int gr1 = gr0 + 8;
        float x20 = g_x2[gr0], x21 = g_x2[gr1];
        #pragma unroll
        for (int nt = 0; nt < 4; nt++) {
            int gc = cj * 64 + rn + nt * 8 + 2 * tid4;
            float xc0 = g_x2[gc], xc1 = g_x2[gc + 1];
            float* c = acc[mt][nt];
            float s00 = x20 + xc0 - 2.f * c[0];
            float s01 = x20 + xc1 - 2.f * c[1];
            float s10 = x21 + xc0 - 2.f * c[2];
            float s11 = x21 + xc1 - 2.f * c[3];
            float v00 = (gr0 != gc     && s00 > 0.f) ? (-0.5f * fast_sqrt(s00)) : 0.f;
            float v01 = (gr0 != gc + 1 && s01 > 0.f) ? (-0.5f * fast_sqrt(s01)) : 0.f;
            float v10 = (gr1 != gc     && s10 > 0.f) ? (-0.5f * fast_sqrt(s10)) : 0.f;
            float v11 = (gr1 != gc + 1 && s11 > 0.f) ? (-0.5f * fast_sqrt(s11)) : 0.f;
            *(float2*)&g_logits[(size_t)gr0 * N + gc] = make_float2(v00, v01);
            *(float2*)&g_logits[(size_t)gr1 * N + gc] = make_float2(v10, v11);
            if (mirror) {
                g_logits[(size_t)gc * N + gr0] = v00;
                g_logits[(size_t)gc * N + gr1] = v10;
                g_logits[(size_t)(gc + 1) * N + gr0] = v01;
                g_logits[(size_t)(gc + 1) * N + gr1] = v11;
            }
        }
    }
}

// ---------------------------------------------------------------------------
// Block scans (NT threads)
// ---------------------------------------------------------------------------
__device__ __forceinline__ int exscan_int(int v, int t, int* total) {
    __shared__ int ws[NWARP];
    __syncthreads();
    int lane = t & 31, w = t >> 5;
    int x = v;
    #pragma unroll
    for (int o = 1; o < 32; o <<= 1) {
        int y = __shfl_up_sync(0xffffffffu, x, o);
        if (lane >= o) x += y;
    }
    if (lane == 31) ws[w] = x;
    __syncthreads();
    if (w == 0) {
        int s = (lane < NWARP) ? ws[lane] : 0;
        #pragma unroll
        for (int o = 1; o < 32; o <<= 1) {
            int y = __shfl_up_sync(0xffffffffu, s, o);
            if (lane >= o) s += y;
        }
        if (lane < NWARP) ws[lane] = s;
    }
    __syncthreads();
    *total = ws[NWARP - 1];
    int off = (w == 0) ? 0 : ws[w - 1];
    return off + x - v;
}

__device__ __forceinline__ float exscan_float(float v, int t, float* total) {
    __shared__ float wsf[NWARP];
    __syncthreads();
    int lane = t & 31, w = t >> 5;
    float x = v;
    #pragma unroll
    for (int o = 1; o < 32; o <<= 1) {
        float y = __shfl_up_sync(0xffffffffu, x, o);
        if (lane >= o) x += y;
    }
    if (lane == 31) wsf[w] = x;
    __syncthreads();
    if (w == 0) {
        float s = (lane < NWARP) ? wsf[lane] : 0.f;
        #pragma unroll
        for (int o = 1; o < 32; o <<= 1) {
            float y = __shfl_up_sync(0xffffffffu, s, o);
            if (lane >= o) s += y;
        }
        if (lane < NWARP) wsf[lane] = s;
    }
    __syncthreads();
    *total = wsf[NWARP - 1];
    float off = (w == 0) ? 0.f : wsf[w - 1];
    return off + x - v;
}

// ---------------------------------------------------------------------------
// Kernel 2 (R10/R13 structure — FROZEN except per-k unroll 2 for MLP):
// count -> prefix -> scatter -> bin sums -> suffix-scan -> per-k pass.
// Last CTA (atomic counter) does the deterministic final reduce.
// ---------------------------------------------------------------------------
__global__ void __launch_bounds__(NT, 3) row_kernel(const float* __restrict__ theta,
                                                    const float* __restrict__ shift,
                                                    float* __restrict__ out) {
    extern __shared__ __align__(16) unsigned char smbase[];
    float2* spair  = (float2*)smbase;                 // N  (scattered {val, ex})
    float*  sufsum = (float*)(spair + N);             // NBINS+1
    int*    A      = (int*)(sufsum + NBINS + 1);      // NBINS+1 (counts/starts/cursor)
    __shared__ double red[NT];
    __shared__ int lastFlag;

    const int i = blockIdx.x;
    const int t = threadIdx.x;
    const int PER = NBINS / NT;  // 8
    const int JPT = N / NT;      // 16

    float vex[JPT];
    float sumLg = 0.f;
    #pragma unroll
    for (int q = 0; q < JPT; q++) {
        int j = t + q * NT;
        float v = g_logits[(size_t)i * N + j];
        sumLg += v;  // diagonal stored as 0
        vex[q] = (j == i) ? 0.f : fast_exp(v);
    }

    float prod = 1.f;
    int eacc = 0, cntk = 0;

    #pragma unroll 1
    for (int mat = 0; mat < 2; mat++) {
        const float* M = mat ? shift : theta;
        const float scale = mat ? (NBINS / 100.0f) : (NBINS / 180.0f);

        float vth[JPT];
        #pragma unroll
        for (int q = 0; q < JPT; q++) vth[q] = M[(size_t)i * N + t + q * NT];

        __syncthreads();  // previous phase done with shared arrays
        for (int b = t; b <= NBINS; b += NT) A[b] = 0;
        __syncthreads();

        // count into A[b+1]
        #pragma unroll
        for (int q = 0; q < JPT; q++) {
            int b = (int)(vth[q] * scale);
            b = b < 0 ? 0 : (b > NBINS - 1 ? NBINS - 1 : b);
            atomicAdd(&A[b + 1], 1);
        }
        __syncthreads();

        {   // in-place exclusive prefix: A[b+1] <- start[b]
            int base = t * PER;
            int c[PER], loc[PER];
            #pragma unroll
            for (int q = 0; q < PER; q++) c[q] = A[base + q + 1];
            int s = 0;
            #pragma unroll
            for (int q = 0; q < PER; q++) { loc[q] = s; s += c[q]; }
            int total;
            int excl = exscan_int(s, t, &total);
            #pragma unroll
            for (int q = 0; q < PER; q++) A[base + q + 1] = excl + loc[q];
        }
        __syncthreads();

        // scatter {val, ex}; cursor A[b+1] -> afterwards A[b] == start[b]
        #pragma unroll
        for (int q = 0; q < JPT; q++) {
            int b = (int)(vth[q] * scale);
            b = b < 0 ? 0 : (b > NBINS - 1 ? NBINS - 1 : b);
            int pos = atomicAdd(&A[b + 1], 1);
            spair[pos] = make_float2(vth[q], vex[q]);
        }
        __syncthreads();

        // per-bin exp sums from scattered data (strided bins, no atomics)
        #pragma unroll 1
        for (int q = 0; q < PER; q++) {
            int b = t + q * NT;
            int p0 = A[b], p1 = A[b + 1];
            float s = 0.f;
            for (int p = p0; p < p1; p++) s += spair[p].y;
            sufsum[b] = s;
        }
        if (t == 0) sufsum[NBINS] = 0.f;
        __syncthreads();

        {   // suffix-sum over bins
            int base = t * PER;
            float loc[PER];
            float tot = 0.f;
            #pragma unroll
            for (int q = PER - 1; q >= 0; q--) { tot += sufsum[base + q]; loc[q] = tot; }
            float total;
            float excl = exscan_float(tot, t, &total);
            float off = total - excl - tot;
            #pragma unroll
            for (int q = 0; q < PER; q++) sufsum[base + q] = loc[q] + off;
        }
        __syncthreads();

        // per-k pass: unroll 2 -> two independent LDS chains in flight
        #pragma unroll 2
        for (int k = t; k < N; k += NT) {
            float2 pk = spair[k];
            if (pk.y == 0.f) continue;  // diagonal marker
            float v = pk.x;
            int b = (int)(v * scale);
            b = b < 0 ? 0 : (b > NBINS - 1 ? NBINS - 1 : b);
            float S = sufsum[b + 1];
            int p1 = A[b + 1];
            for (int p = A[b]; p < p1; p++) {
                float2 pq = spair[p];
                if (pq.x >= v) S += pq.y;
            }
            prod *= S;
            unsigned pb = __float_as_uint(prod);
            eacc += (int)(pb >> 23);
            prod = __uint_as_float((pb & 0x007fffffu) | 0x3f800000u);
            cntk++;
        }
    }

    double logsum = ((double)(eacc - 127 * cntk)) * 0.6931471805599453
                  + (double)__logf(prod);
    __syncthreads();
    red[t] = (double)sumLg - 0.5 * logsum;
    __syncthreads();
    #pragma unroll
    for (int o = NT / 2; o; o >>= 1) {
        if (t < o) red[t] += red[t + o];
        __syncthreads();
    }
    if (t == 0) {
        g_rowsum[i] = red[0];
        __threadfence();
        lastFlag = (atomicAdd(&g_done, 1) == N - 1);
    }
    __syncthreads();

    if (lastFlag) {   // last CTA: deterministic final reduce
        __threadfence();
        double s = 0.0;
        for (int r = t; r < N; r += NT) s += g_rowsum[r];
        red[t] = s;
        __syncthreads();
        #pragma unroll
        for (int o = NT / 2; o; o >>= 1) {
            if (t < o) red[t] += red[t + o];
            __syncthreads();
        }
        if (t == 0)
            out[0] = (float)(-red[0] / ((double)N * (double)(N - 1)));
    }
}

// ---------------------------------------------------------------------------
extern "C" void kernel_launch(void* const* d_in, const int* in_sizes, int n_in,
                              void* d_out, int out_size) {
    const float* theta = (const float*)d_in[0];
    const float* shift = (const float*)d_in[1];
    const float* feats = (const float*)d_in[2];
    float* out = (float*)d_out;

    size_t gram_smem = (2 * 128 + 2 * 64) * PITCH * sizeof(float);  // 55296
    size_t row_smem  = (size_t)N * 8 + (NBINS + 1) * 4 + (NBINS + 1) * 4;
    cudaFuncSetAttribute(gram_kernel, cudaFuncAttributeMaxDynamicSharedMemorySize, (int)gram_smem);
    cudaFuncSetAttribute(row_kernel, cudaFuncAttributeMaxDynamicSharedMemorySize, (int)row_smem);

    prep_kernel<<<N, 128>>>(feats);                      // launch 1

    gram_kernel<<<NGRAM, 256, gram_smem>>>();            // launch 2

    nop_kernel<<<1, 1>>>();                              // launch 3

    row_kernel<<<N, NT, row_smem>>>(theta, shift, out);  // launch 4 <- ncu
}

// round 17
// speedup vs baseline: 1.0482x; 1.0482x over previous
#include <cuda_runtime.h>
#include <cuda_bf16.h>
#include <math.h>
#include <cstdint>

#define N 4096
#define D 128
#define NBINS 2048
#define NT 256
#define NWARP (NT / 32)
#define CTILES 64                 // N/64  (col tiles)
#define NGRAM 1056                // sum_{bi}(64-2bi)
#define PITCHB 40                 // smem row pitch in bf16 (80B -> 20-word stride)

__device__ float          g_logits[(size_t)N * N];  // 64 MB scratch
__device__ __nv_bfloat16  g_fhi[(size_t)N * D];     // bf16 hi part
__device__ __nv_bfloat16  g_flo[(size_t)N * D];     // bf16 residual
__device__ float          g_x2[N];
__device__ double         g_rowsum[N];
__device__ int            g_done;

// ---------------------------------------------------------------------------
// fast math on FMA/ALU pipes (MUFU avoidance)
// ---------------------------------------------------------------------------
__device__ __forceinline__ float fast_sqrt(float x) {
    float xh = 0.5f * x;
    float y = __int_as_float(0x5f375a86 - (__float_as_int(x) >> 1));
    y = y * fmaf(-xh * y, y, 1.5f);
    y = y * fmaf(-xh * y, y, 1.5f);
    y = y * fmaf(-xh * y, y, 1.5f);
    return x * y;
}
__device__ __forceinline__ float fast_exp(float x) {
    float t = x * 1.4426950408889634f;
    float n = rintf(t);
    float f = t - n;
    float p = fmaf(f, 1.5403530e-4f, 0.0013333558f);
    p = fmaf(f, p, 0.0096181291f);
    p = fmaf(f, p, 0.0555041087f);
    p = fmaf(f, p, 0.2402265069f);
    p = fmaf(f, p, 0.6931471806f);
    p = fmaf(f, p, 1.0f);
    return __int_as_float(((int)n + 127) << 23) * p;
}

// ---------------------------------------------------------------------------
// Kernel 0: x2 + bf16 hi/lo split + counter reset
// ---------------------------------------------------------------------------
__global__ void prep_kernel(const float* __restrict__ F) {
    int i = blockIdx.x, t = threadIdx.x;
    if (i == 0 && t == 0) g_done = 0;
    float x = F[(size_t)i * D + t];
    __nv_bfloat16 hi = __float2bfloat16(x);
    __nv_bfloat16 lo = __float2bfloat16(x - __bfloat162float(hi));
    g_fhi[(size_t)i * D + t] = hi;
    g_flo[(size_t)i * D + t] = lo;
    float v = x * x;
    __shared__ float s[4];
    #pragma unroll
    for (int o = 16; o; o >>= 1) v += __shfl_down_sync(0xffffffffu, v, o);
    if ((t & 31) == 0) s[t >> 5] = v;
    __syncthreads();
    if (t == 0) g_x2[i] = s[0] + s[1] + s[2] + s[3];
}

// profiler-alignment spacer (ncu profiles absolute launch #4)
__global__ void nop_kernel() {}

// ---------------------------------------------------------------------------
// Kernel 1: bf16-split tensor-core Gram (m16n8k16), 128x64 tiles,
// warp tiling (mt,nt)=(2,4). Tiles (bi, cj) with cj >= 2*bi: diagonal-
// straddling pair computed fully, strict-upper tiles mirrored.
// ---------------------------------------------------------------------------
#define MMA_BF16(c, a, b) \
    asm volatile("mma.sync.aligned.m16n8k16.row.col.f32.bf16.bf16.f32 " \
        "{%0,%1,%2,%3}, {%4,%5,%6,%7}, {%8,%9}, {%0,%1,%2,%3};" \
        : "+f"((c)[0]), "+f"((c)[1]), "+f"((c)[2]), "+f"((c)[3]) \
        : "r"((a)[0]), "r"((a)[1]), "r"((a)[2]), "r"((a)[3]), \
          "r"((b)[0]), "r"((b)[1]))

__global__ void __launch_bounds__(256, 2) gram_kernel() {
    // decode linear index -> (bi, cj), cj in [2*bi, 64)
    int idx = blockIdx.x;
    int bi = 0;
    #pragma unroll 1
    for (;; bi++) {
        int cnt = CTILES - 2 * bi;
        if (idx < cnt) break;
        idx -= cnt;
    }
    int cj = 2 * bi + idx;
    bool mirror = (cj >= 2 * bi + 2);

    extern __shared__ __align__(16) __nv_bfloat16 smb[];
    __nv_bfloat16* Ah = smb;                   // 128 x PITCHB
    __nv_bfloat16* Al = Ah + 128 * PITCHB;
    __nv_bfloat16* Bh = Al + 128 * PITCHB;     // 64 x PITCHB
    __nv_bfloat16* Bl = Bh + 64 * PITCHB;

    const int t = threadIdx.x;
    const int wid = t >> 5, lane = t & 31;
    const int g = lane >> 2, tid4 = lane & 3;
    const int rm = (wid & 3) * 32;             // warp row base (0,32,64,96)
    const int rn = (wid >> 2) * 32;            // warp col base (0 or 32)

    float acc[2][4][4];
    #pragma unroll
    for (int mt = 0; mt < 2; mt++)
        #pragma unroll
        for (int nt = 0; nt < 4; nt++)
            #pragma unroll
            for (int e = 0; e < 4; e++) acc[mt][nt][e] = 0.f;

    #pragma unroll 1
    for (int kc = 0; kc < 4; kc++) {
        int k0 = kc * 32;
        __syncthreads();
        // A tiles: 128 rows x 4 uint4-chunks (32 bf16/row), hi+lo
        #pragma unroll
        for (int p = 0; p < 2; p++) {
            int id = t + p * 256;
            int row = id >> 2, cg = id & 3;
            size_t arow = (size_t)(bi * 128 + row) * D + k0 + cg * 8;
            *(uint4*)&Ah[row * PITCHB + cg * 8] = *(const uint4*)(g_fhi + arow);
            *(uint4*)&Al[row * PITCHB + cg * 8] = *(const uint4*)(g_flo + arow);
        }
        // B tiles: 64 rows x 4 chunks, hi+lo
        {
            int row = t >> 2, cg = t & 3;
            size_t brow = (size_t)(cj * 64 + row) * D + k0 + cg * 8;
            *(uint4*)&Bh[row * PITCHB + cg * 8] = *(const uint4*)(g_fhi + brow);
            *(uint4*)&Bl[row * PITCHB + cg * 8] = *(const uint4*)(g_flo + brow);
        }
        __syncthreads();

        #pragma unroll
        for (int ks = 0; ks < 2; ks++) {
            int kk = ks * 16;
            uint32_t afH[2][4], afL[2][4];
            #pragma unroll
            for (int mt = 0; mt < 2; mt++) {
                int r0 = rm + mt * 16 + g;
                int o0 = r0 * PITCHB + kk + 2 * tid4;
                int o1 = (r0 + 8) * PITCHB + kk + 2 * tid4;
                afH[mt][0] = *(const uint32_t*)&Ah[o0];
                afH[mt][1] = *(const uint32_t*)&Ah[o1];
                afH[mt][2] = *(const uint32_t*)&Ah[o0 + 8];
                afH[mt][3] = *(const uint32_t*)&Ah[o1 + 8];
                afL[mt][0] = *(const uint32_t*)&Al[o0];
                afL[mt][1] = *(const uint32_t*)&Al[o1];
                afL[mt][2] = *(const uint32_t*)&Al[o0 + 8];
                afL[mt][3] = *(const uint32_t*)&Al[o1 + 8];
            }
            uint32_t bfH[4][2], bfL[4][2];
            #pragma unroll
            for (int nt = 0; nt < 4; nt++) {
                int nc = rn + nt * 8 + g;
                int o = nc * PITCHB + kk + 2 * tid4;
                bfH[nt][0] = *(const uint32_t*)&Bh[o];
                bfH[nt][1] = *(const uint32_t*)&Bh[o + 8];
                bfL[nt][0] = *(const uint32_t*)&Bl[o];
                bfL[nt][1] = *(const uint32_t*)&Bl[o + 8];
            }
            #pragma unroll
            for (int mt = 0; mt < 2; mt++)
                #pragma unroll
                for (int nt = 0; nt < 4; nt++) {
                    MMA_BF16(acc[mt][nt], afH[mt], bfH[nt]);
                    MMA_BF16(acc[mt][nt], afH[mt], bfL[nt]);
                    MMA_BF16(acc[mt][nt], afL[mt], bfH[nt]);
                }
        }
    }

    // epilogue: logits = -0.5*sqrt(x2i + x2j - 2*dot); optional mirror
    #pragma unroll
    for (int mt = 0; mt < 2; mt++) {
        int gr0 = bi * 128 + rm + mt * 16 + g;
        int gr1 = gr0 + 8;
        float x20 = g_x2[gr0], x21 = g_x2[gr1];
        #pragma unroll
        for (int nt = 0; nt < 4; nt++) {
            int gc = cj * 64 + rn + nt * 8 + 2 * tid4;
            float xc0 = g_x2[gc], xc1 = g_x2[gc + 1];
            float* c = acc[mt][nt];
            float s00 = x20 + xc0 - 2.f * c[0];
            float s01 = x20 + xc1 - 2.f * c[1];
            float s10 = x21 + xc0 - 2.f * c[2];
            float s11 = x21 + xc1 - 2.f * c[3];
            float v00 = (gr0 != gc     && s00 > 0.f) ? (-0.5f * fast_sqrt(s00)) : 0.f;
            float v01 = (gr0 != gc + 1 && s01 > 0.f) ? (-0.5f * fast_sqrt(s01)) : 0.f;
            float v10 = (gr1 != gc     && s10 > 0.f) ? (-0.5f * fast_sqrt(s10)) : 0.f;
            float v11 = (gr1 != gc + 1 && s11 > 0.f) ? (-0.5f * fast_sqrt(s11)) : 0.f;
            *(float2*)&g_logits[(size_t)gr0 * N + gc] = make_float2(v00, v01);
            *(float2*)&g_logits[(size_t)gr1 * N + gc] = make_float2(v10, v11);
            if (mirror) {
                g_logits[(size_t)gc * N + gr0] = v00;
                g_logits[(size_t)gc * N + gr1] = v10;
                g_logits[(size_t)(gc + 1) * N + gr0] = v01;
                g_logits[(size_t)(gc + 1) * N + gr1] = v11;
            }
        }
    }
}

// ---------------------------------------------------------------------------
// Block scans (NT threads)
// ---------------------------------------------------------------------------
__device__ __forceinline__ int exscan_int(int v, int t, int* total) {
    __shared__ int ws[NWARP];
    __syncthreads();
    int lane = t & 31, w = t >> 5;
    int x = v;
    #pragma unroll
    for (int o = 1; o < 32; o <<= 1) {
        int y = __shfl_up_sync(0xffffffffu, x, o);
        if (lane >= o) x += y;
    }
    if (lane == 31) ws[w] = x;
    __syncthreads();
    if (w == 0) {
        int s = (lane < NWARP) ? ws[lane] : 0;
        #pragma unroll
        for (int o = 1; o < 32; o <<= 1) {
            int y = __shfl_up_sync(0xffffffffu, s, o);
            if (lane >= o) s += y;
        }
        if (lane < NWARP) ws[lane] = s;
    }
    __syncthreads();
    *total = ws[NWARP - 1];
    int off = (w == 0) ? 0 : ws[w - 1];
    return off + x - v;
}

__device__ __forceinline__ float exscan_float(float v, int t, float* total) {
    __shared__ float wsf[NWARP];
    __syncthreads();
    int lane = t & 31, w = t >> 5;
    float x = v;
    #pragma unroll
    for (int o = 1; o < 32; o <<= 1) {
        float y = __shfl_up_sync(0xffffffffu, x, o);
        if (lane >= o) x += y;
    }
    if (lane == 31) wsf[w] = x;
    __syncthreads();
    if (w == 0) {
        float s = (lane < NWARP) ? wsf[lane] : 0.f;
        #pragma unroll
        for (int o = 1; o < 32; o <<= 1) {
            float y = __shfl_up_sync(0xffffffffu, s, o);
            if (lane >= o) s += y;
        }
        if (lane < NWARP) wsf[lane] = s;
    }
    __syncthreads();
    *total = wsf[NWARP - 1];
    float off = (w == 0) ? 0.f : wsf[w - 1];
    return off + x - v;
}

// ---------------------------------------------------------------------------
// Kernel 2 (FROZEN): count -> prefix -> scatter -> bin sums -> suffix-scan
// -> per-k pass. Last CTA (atomic counter) does the deterministic reduce.
// ---------------------------------------------------------------------------
__global__ void __launch_bounds__(NT, 3) row_kernel(const float* __restrict__ theta,
                                                    const float* __restrict__ shift,
                                                    float* __restrict__ out) {
    extern __shared__ __align__(16) unsigned char smbase[];
    float2* spair  = (float2*)smbase;                 // N  (scattered {val, ex})
    float*  sufsum = (float*)(spair + N);             // NBINS+1
    int*    A      = (int*)(sufsum + NBINS + 1);      // NBINS+1 (counts/starts/cursor)
    __shared__ double red[NT];
    __shared__ int lastFlag;

    const int i = blockIdx.x;
    const int t = threadIdx.x;
    const int PER = NBINS / NT;  // 8
    const int JPT = N / NT;      // 16

    float vex[JPT];
    float sumLg = 0.f;
    #pragma unroll
    for (int q = 0; q < JPT; q++) {
        int j = t + q * NT;
        float v = g_logits[(size_t)i * N + j];
        sumLg += v;  // diagonal stored as 0
        vex[q] = (j == i) ? 0.f : fast_exp(v);
    }

    float prod = 1.f;
    int eacc = 0, cntk = 0;

    #pragma unroll 1
    for (int mat = 0; mat < 2; mat++) {
        const float* M = mat ? shift : theta;
        const float scale = mat ? (NBINS / 100.0f) : (NBINS / 180.0f);

        float vth[JPT];
        #pragma unroll
        for (int q = 0; q < JPT; q++) vth[q] = M[(size_t)i * N + t + q * NT];

        __syncthreads();  // previous phase done with shared arrays
        for (int b = t; b <= NBINS; b += NT) A[b] = 0;
        __syncthreads();

        // count into A[b+1]
        #pragma unroll
        for (int q = 0; q < JPT; q++) {
            int b = (int)(vth[q] * scale);
            b = b < 0 ? 0 : (b > NBINS - 1 ? NBINS - 1 : b);
            atomicAdd(&A[b + 1], 1);
        }
        __syncthreads();

        {   // in-place exclusive prefix: A[b+1] <- start[b]
            int base = t * PER;
            int c[PER], loc[PER];
            #pragma unroll
            for (int q = 0; q < PER; q++) c[q] = A[base + q + 1];
            int s = 0;
            #pragma unroll
            for (int q = 0; q < PER; q++) { loc[q] = s; s += c[q]; }
            int total;
            int excl = exscan_int(s, t, &total);
            #pragma unroll
            for (int q = 0; q < PER; q++) A[base + q + 1] = excl + loc[q];
        }
        __syncthreads();

        // scatter {val, ex}; cursor A[b+1] -> afterwards A[b] == start[b]
        #pragma unroll
        for (int q = 0; q < JPT; q++) {
            int b = (int)(vth[q] * scale);
            b = b < 0 ? 0 : (b > NBINS - 1 ? NBINS - 1 : b);
            int pos = atomicAdd(&A[b + 1], 1);
            spair[pos] = make_float2(vth[q], vex[q]);
        }
        __syncthreads();

        // per-bin exp sums from scattered data (strided bins, no atomics)
        #pragma unroll 1
        for (int q = 0; q < PER; q++) {
            int b = t + q * NT;
            int p0 = A[b], p1 = A[b + 1];
            float s = 0.f;
            for (int p = p0; p < p1; p++) s += spair[p].y;
            sufsum[b] = s;
        }
        if (t == 0) sufsum[NBINS] = 0.f;
        __syncthreads();

        {   // suffix-sum over bins
            int base = t * PER;
            float loc[PER];
            float tot = 0.f;
            #pragma unroll
            for (int q = PER - 1; q >= 0; q--) { tot += sufsum[base + q]; loc[q] = tot; }
            float total;
            float excl = exscan_float(tot, t, &total);
            float off = total - excl - tot;
            #pragma unroll
            for (int q = 0; q < PER; q++) sufsum[base + q] = loc[q] + off;
        }
        __syncthreads();

        // per-k pass: unroll 2 -> two independent LDS chains in flight
        #pragma unroll 2
        for (int k = t; k < N; k += NT) {
            float2 pk = spair[k];
            if (pk.y == 0.f) continue;  // diagonal marker
            float v = pk.x;
            int b = (int)(v * scale);
            b = b < 0 ? 0 : (b > NBINS - 1 ? NBINS - 1 : b);
            float S = sufsum[b + 1];
            int p1 = A[b + 1];
            for (int p = A[b]; p < p1; p++) {
                float2 pq = spair[p];
                if (pq.x >= v) S += pq.y;
            }
            prod *= S;
            unsigned pb = __float_as_uint(prod);
            eacc += (int)(pb >> 23);
            prod = __uint_as_float((pb & 0x007fffffu) | 0x3f800000u);
            cntk++;
        }
    }

    double logsum = ((double)(eacc - 127 * cntk)) * 0.6931471805599453
                  + (double)__logf(prod);
    __syncthreads();
    red[t] = (double)sumLg - 0.5 * logsum;
    __syncthreads();
    #pragma unroll
    for (int o = NT / 2; o; o >>= 1) {
        if (t < o) red[t] += red[t + o];
        __syncthreads();
    }
    if (t == 0) {
        g_rowsum[i] = red[0];
        __threadfence();
        lastFlag = (atomicAdd(&g_done, 1) == N - 1);
    }
    __syncthreads();

    if (lastFlag) {   // last CTA: deterministic final reduce
        __threadfence();
        double s = 0.0;
        for (int r = t; r < N; r += NT) s += g_rowsum[r];
        red[t] = s;
        __syncthreads();
        #pragma unroll
        for (int o = NT / 2; o; o >>= 1) {
            if (t < o) red[t] += red[t + o];
            __syncthreads();
        }
        if (t == 0)
            out[0] = (float)(-red[0] / ((double)N * (double)(N - 1)));
    }
}

// ---------------------------------------------------------------------------
extern "C" void kernel_launch(void* const* d_in, const int* in_sizes, int n_in,
                              void* d_out, int out_size) {
    const float* theta = (const float*)d_in[0];
    const float* shift = (const float*)d_in[1];
    const float* feats = (const float*)d_in[2];
    float* out = (float*)d_out;

    size_t gram_smem = (size_t)(2 * 128 + 2 * 64) * PITCHB * sizeof(__nv_bfloat16); // 30720
    size_t row_smem  = (size_t)N * 8 + (NBINS + 1) * 4 + (NBINS + 1) * 4;
    cudaFuncSetAttribute(gram_kernel, cudaFuncAttributeMaxDynamicSharedMemorySize, (int)gram_smem);
    cudaFuncSetAttribute(row_kernel, cudaFuncAttributeMaxDynamicSharedMemorySize, (int)row_smem);

    prep_kernel<<<N, 128>>>(feats);                      // launch 1
    nop_kernel<<<1, 1>>>();                              // launch 2
    nop_kernel<<<1, 1>>>();                              // launch 3

    gram_kernel<<<NGRAM, 256, gram_smem>>>();            // launch 4 <- ncu

    row_kernel<<<N, NT, row_smem>>>(theta, shift, out);  // launch 5
}